// round 14
// baseline (speedup 1.0000x reference)
#include <cuda_runtime.h>
#include <cuda_fp16.h>
#include <math.h>
#include <stdint.h>

// Problem constants
#define NN   25600
#define EE   409600
#define GG   128
#define INF_ 200
#define HC4  256
#define ETOT (EE + NN)
#define KP0  448            // padded K for layer-0 GEMM (400 -> 448)

#define NEG_BIG (-1.0e30f)

// ---------------- scratch ----------------
__device__ __align__(16) __half d_hh [(size_t)NN * HC4];     // GEMM output (fp16)
__device__ __align__(16) __half d_x  [(size_t)NN * HC4];     // layer 1/2 GEMM A (fp16)
__device__ __align__(16) __half d_a0 [(size_t)NN * KP0];     // layer 0 GEMM A (fp16)
__device__ __align__(16) __half d_b0 [256 * KP0];
__device__ __align__(16) __half d_b1 [256 * 256];
__device__ __align__(16) __half d_b2 [64 * 256];
__device__ __align__(16) float d_asb[NN * 4];
__device__ __align__(16) float d_adb[NN * 4];
__device__ int   d_cnt[NN];
__device__ int   d_fill[NN];
__device__ float d_easum[NN];
__device__ int   d_rowptr[NN + 1];
__device__ int   d_csrc[ETOT];
__device__ float d_cea [ETOT];
__device__ float d_gsum[GG * 64];
__device__ float d_gcnt[GG];
__device__ float d_wd[9];

// ---------------- helpers ----------------
__device__ __forceinline__ uint32_t smem_u32(const void* p) {
    uint32_t a;
    asm("{ .reg .u64 t; cvta.to.shared.u64 t, %1; cvt.u32.u64 %0, t; }" : "=r"(a) : "l"(p));
    return a;
}
__device__ __forceinline__ float warp_sum(float v) {
    #pragma unroll
    for (int o = 16; o; o >>= 1) v += __shfl_xor_sync(0xffffffffu, v, o);
    return v;
}
__device__ __forceinline__ void cp16(uint32_t smem, const void* g) {
    asm volatile("cp.async.cg.shared.global [%0], [%1], 16;" :: "r"(smem), "l"(g) : "memory");
}
__device__ __forceinline__ void ldsm4(uint32_t* r, uint32_t addr) {
    asm volatile("ldmatrix.sync.aligned.m8n8.x4.shared.b16 {%0,%1,%2,%3}, [%4];"
                 : "=r"(r[0]), "=r"(r[1]), "=r"(r[2]), "=r"(r[3]) : "r"(addr));
}
__device__ __forceinline__ void mma16816(float* d, const uint32_t* a, const uint32_t* b) {
    asm volatile("mma.sync.aligned.m16n8k16.row.col.f32.f16.f16.f32 "
                 "{%0,%1,%2,%3}, {%4,%5,%6,%7}, {%8,%9}, {%0,%1,%2,%3};"
                 : "+f"(d[0]), "+f"(d[1]), "+f"(d[2]), "+f"(d[3])
                 : "r"(a[0]), "r"(a[1]), "r"(a[2]), "r"(a[3]), "r"(b[0]), "r"(b[1]));
}

// ---------------- K1: prep = zero + xsplit + wsplit0/1/2 ----------------
__global__ __launch_bounds__(256) void prep_kernel(const float* __restrict__ x,
                                                   const float* __restrict__ W0,
                                                   const float* __restrict__ W1,
                                                   const float* __restrict__ W2) {
    const long ZN = NN;
    const long ZG = GG * 64 + GG;
    const long XS = (long)NN * KP0;
    const long WS0 = 256 * KP0, WS1 = 256 * 256, WS2 = 64 * 256;
    const long total = ZN + ZG + XS + WS0 + WS1 + WS2;
    for (long i = (long)blockIdx.x * blockDim.x + threadIdx.x; i < total;
         i += (long)gridDim.x * blockDim.x) {
        long r = i;
        if (r < ZN) { d_cnt[r] = 0; d_fill[r] = 0; d_easum[r] = 0.f; continue; }
        r -= ZN;
        if (r < ZG) { if (r < GG * 64) d_gsum[r] = 0.f; else d_gcnt[r - GG * 64] = 0.f; continue; }
        r -= ZG;
        if (r < XS) {
            int n = (int)(r / KP0), kk = (int)(r % KP0);
            float v = 0.f;
            if (kk < INF_)        { float t = x[n * INF_ + kk];        v = (t != t) ? 0.f : t; }
            else if (kk < 2*INF_) { float t = x[n * INF_ + kk - INF_]; v = (t != t) ? 1.f : 0.f; }
            d_a0[r] = __float2half_rn(v);
            continue;
        }
        r -= XS;
        if (r < WS0) {
            int n = (int)(r / KP0), k = (int)(r % KP0);
            d_b0[r] = __float2half_rn((k < 400) ? W0[k * 256 + n] : 0.f);
            continue;
        }
        r -= WS0;
        if (r < WS1) {
            int n = (int)(r / 256), k = (int)(r % 256);
            d_b1[r] = __float2half_rn(W1[k * 256 + n]);
            continue;
        }
        r -= WS1;
        {
            int n = (int)(r / 256), k = (int)(r % 256);
            d_b2[r] = __float2half_rn(W2[k * 64 + n]);
        }
    }
}

// ---------------- HMMA fp16 GEMM + fused attn scalars (+optional edge-count tail) ----------------
// Epilogue computes a_s/a_d per (row, head) from the fp32 accumulators:
// each block exclusively owns rows [m0,m0+128) x heads [n0/64, n0/64+BN/64).
template <int BN, int NSTR, int KPAD, int SEL, bool XCNT>
__global__ __launch_bounds__(256, 2) void hmma_gemm(const int* __restrict__ ei,
                                                    const float* __restrict__ ea,
                                                    const float* __restrict__ att_s,
                                                    const float* __restrict__ att_d) {
    if (XCNT && blockIdx.y >= 200) {
        int cb = (blockIdx.y - 200) * 2 + blockIdx.x;
        for (int e = cb * 256 + threadIdx.x; e < EE; e += 200 * 256) {
            int dd = ei[EE + e];
            float v = ea[e];
            if (v != v) v = 0.f;
            atomicAdd(&d_cnt[dd], 1);
            atomicAdd(&d_easum[dd], v);
        }
        return;
    }

    constexpr int WM = 4;
    constexpr int WN = BN / 32;
    constexpr int PITCH = 80;
    constexpr int ATILE = 128 * PITCH;
    constexpr int BTILE = BN * PITCH;
    constexpr int BUFSZ = ATILE + BTILE;
    constexpr int NCH = KPAD / 32;
    constexpr int ROWB = KPAD * 2;
    constexpr int HLOC = BN / 64;      // heads owned by this block (2 or 1)
    constexpr int HATT = NSTR / 64;    // total heads (4 or 1)

    const __half* Af = (SEL == 0) ? d_a0 : d_x;
    const __half* Bf = (SEL == 0) ? d_b0 : (SEL == 1 ? d_b1 : d_b2);

    extern __shared__ __align__(16) char dsm[];
    uint32_t sb = smem_u32(dsm);

    int tid = threadIdx.x, wid = tid >> 5, lane = tid & 31;
    int m0 = blockIdx.y * 128, n0 = blockIdx.x * BN;
    int mb = (wid >> 2) * 64;
    int nb = (wid & 3) * WN * 8;

    const char* gA = (const char*)Af + (size_t)m0 * ROWB;
    const char* gB = (const char*)Bf + (size_t)n0 * ROWB;

    auto issue = [&](int c, int b) {
        uint32_t base = sb + b * BUFSZ;
        int cb = c * 64;
        #pragma unroll
        for (int i = tid; i < 512; i += 256) {
            int r = i >> 2, u = (i & 3) * 16;
            cp16(base + r * PITCH + u, gA + (size_t)r * ROWB + cb + u);
        }
        #pragma unroll
        for (int i = tid; i < BN * 4; i += 256) {
            int r = i >> 2, u = (i & 3) * 16;
            cp16(base + ATILE + r * PITCH + u, gB + (size_t)r * ROWB + cb + u);
        }
        asm volatile("cp.async.commit_group;" ::: "memory");
    };

    float acc[WM][WN][4];
    #pragma unroll
    for (int i = 0; i < WM; i++)
        #pragma unroll
        for (int j = 0; j < WN; j++)
            #pragma unroll
            for (int q = 0; q < 4; q++) acc[i][j][q] = 0.f;

    uint32_t a_ln = (lane & 15) * PITCH + (lane >> 4) * 16;
    uint32_t b_ln = ((lane & 7) + ((lane >> 4) << 3)) * PITCH + ((lane >> 3) & 1) * 16;

    issue(0, 0);
    for (int c = 0; c < NCH; c++) {
        int buf = c & 1;
        if (c + 1 < NCH) {
            issue(c + 1, buf ^ 1);
            asm volatile("cp.async.wait_group 1;" ::: "memory");
        } else {
            asm volatile("cp.async.wait_group 0;" ::: "memory");
        }
        __syncthreads();

        uint32_t base  = sb + buf * BUFSZ;
        uint32_t a_row = base + mb * PITCH + a_ln;
        uint32_t b_row = base + ATILE + nb * PITCH + b_ln;

        #pragma unroll
        for (int ks = 0; ks < 2; ks++) {
            uint32_t bf[WN / 2][4];
            #pragma unroll
            for (int nt2 = 0; nt2 < WN / 2; nt2++)
                ldsm4(bf[nt2], b_row + nt2 * 16 * PITCH + ks * 32);
            #pragma unroll
            for (int mt = 0; mt < WM; mt++) {
                uint32_t af[4];
                ldsm4(af, a_row + mt * 16 * PITCH + ks * 32);
                #pragma unroll
                for (int nt = 0; nt < WN; nt++)
                    mma16816(acc[mt][nt], af, &bf[nt >> 1][(nt & 1) * 2]);
            }
        }
        __syncthreads();
    }

    // ---- write fp16 result ----
    int r0 = m0 + mb + (lane >> 2);
    int c0 = n0 + nb + (lane & 3) * 2;
    #pragma unroll
    for (int mt = 0; mt < WM; mt++)
        #pragma unroll
        for (int nt = 0; nt < WN; nt++) {
            int rr = r0 + mt * 16, cc = c0 + nt * 8;
            __half2 p01 = __floats2half2_rn(acc[mt][nt][0], acc[mt][nt][1]);
            __half2 p23 = __floats2half2_rn(acc[mt][nt][2], acc[mt][nt][3]);
            *(__half2*)&d_hh[(size_t)rr * NSTR + cc]       = p01;
            *(__half2*)&d_hh[(size_t)(rr + 8) * NSTR + cc] = p23;
        }

    // ---- fused attention scalars: a_s/a_d per (row, head) ----
    float pS[2 * WM], pD[2 * WM];
    #pragma unroll
    for (int i = 0; i < 2 * WM; i++) { pS[i] = 0.f; pD[i] = 0.f; }
    #pragma unroll
    for (int nt = 0; nt < WN; nt++) {
        int cc = c0 + nt * 8;             // global channel
        float s0 = att_s[cc], s1 = att_s[cc + 1];
        float e0 = att_d[cc], e1 = att_d[cc + 1];
        #pragma unroll
        for (int mt = 0; mt < WM; mt++) {
            pS[2 * mt]     += acc[mt][nt][0] * s0 + acc[mt][nt][1] * s1;
            pS[2 * mt + 1] += acc[mt][nt][2] * s0 + acc[mt][nt][3] * s1;
            pD[2 * mt]     += acc[mt][nt][0] * e0 + acc[mt][nt][1] * e1;
            pD[2 * mt + 1] += acc[mt][nt][2] * e0 + acc[mt][nt][3] * e1;
        }
    }
    // reduce over the 4 col-groups of the warp (lane bits 0-1)
    #pragma unroll
    for (int i = 0; i < 2 * WM; i++) {
        pS[i] += __shfl_xor_sync(0xffffffffu, pS[i], 1);
        pS[i] += __shfl_xor_sync(0xffffffffu, pS[i], 2);
        pD[i] += __shfl_xor_sync(0xffffffffu, pD[i], 1);
        pD[i] += __shfl_xor_sync(0xffffffffu, pD[i], 2);
    }
    // cross-warp combine in smem (GEMM tiles no longer needed)
    float* s_at = (float*)dsm;            // [128][HLOC][2]
    for (int i = tid; i < 128 * HLOC * 2; i += 256) s_at[i] = 0.f;
    __syncthreads();
    if ((lane & 3) == 0) {
        int lh = nb >> 6;                 // local head of this warp's columns
        int rbase = mb + (lane >> 2);
        #pragma unroll
        for (int mt = 0; mt < WM; mt++) {
            int rl0 = rbase + mt * 16, rl1 = rl0 + 8;
            atomicAdd(&s_at[(rl0 * HLOC + lh) * 2 + 0], pS[2 * mt]);
            atomicAdd(&s_at[(rl0 * HLOC + lh) * 2 + 1], pD[2 * mt]);
            atomicAdd(&s_at[(rl1 * HLOC + lh) * 2 + 0], pS[2 * mt + 1]);
            atomicAdd(&s_at[(rl1 * HLOC + lh) * 2 + 1], pD[2 * mt + 1]);
        }
    }
    __syncthreads();
    for (int i = tid; i < 128 * HLOC; i += 256) {
        int rl = i / HLOC, lh = i % HLOC;
        int hg = (n0 >> 6) + lh;
        d_asb[(m0 + rl) * HATT + hg] = s_at[i * 2 + 0];
        d_adb[(m0 + rl) * HATT + hg] = s_at[i * 2 + 1];
    }
}

// ---------------- K3: scan (block 0) + wd (block 1) ----------------
__global__ __launch_bounds__(1024) void swa_kernel(
    const float* We0, const float* ae0,
    const float* We1, const float* ae1,
    const float* We2, const float* ae2) {
    int tid = threadIdx.x, lane = tid & 31, wid = tid >> 5;

    if (blockIdx.x == 0) {
        __shared__ int wsum[32];
        __shared__ int s_off;
        if (tid == 0) { d_rowptr[0] = 0; s_off = 0; }
        __syncthreads();
        for (int base = 0; base < NN; base += 1024) {
            int inc = d_cnt[base + tid] + 1;
            #pragma unroll
            for (int o = 1; o < 32; o <<= 1) {
                int t = __shfl_up_sync(0xffffffffu, inc, o);
                if (lane >= o) inc += t;
            }
            if (lane == 31) wsum[wid] = inc;
            __syncthreads();
            if (wid == 0) {
                int wi = wsum[lane];
                #pragma unroll
                for (int o = 1; o < 32; o <<= 1) {
                    int t = __shfl_up_sync(0xffffffffu, wi, o);
                    if (lane >= o) wi += t;
                }
                wsum[lane] = wi;
            }
            __syncthreads();
            int excl_w = wid ? wsum[wid - 1] : 0;
            d_rowptr[base + tid + 1] = s_off + excl_w + inc;
            __syncthreads();
            if (tid == 0) s_off += wsum[31];
            __syncthreads();
        }
        return;
    }
    // we_dot
    if (wid >= 9) return;
    const float *We, *ae; int h;
    if (wid < 4)      { We = We0; ae = ae0; h = wid; }
    else if (wid < 8) { We = We1; ae = ae1; h = wid - 4; }
    else              { We = We2; ae = ae2; h = 0; }
    float s = 0.f;
    for (int c = lane; c < 64; c += 32) s += We[h * 64 + c] * ae[h * 64 + c];
    s = warp_sum(s);
    if (lane == 0) d_wd[wid] = s;
}

// ---------------- K4: fill (blocks 0..799) + selfloop (blocks 800..899) ----------------
__global__ __launch_bounds__(256) void fillself_kernel(const int* __restrict__ ei,
                                                       const float* __restrict__ ea) {
    int b = blockIdx.x;
    if (b < 800) {
        for (int e = b * 256 + threadIdx.x; e < EE; e += 800 * 256) {
            int s = ei[e], d = ei[EE + e];
            float v = ea[e];
            if (v != v) v = 0.f;
            int pos = d_rowptr[d] + atomicAdd(&d_fill[d], 1);
            d_csrc[pos] = s;
            d_cea[pos]  = v;
        }
    } else {
        int n = (b - 800) * 256 + threadIdx.x;
        if (n >= NN) return;
        int pos = d_rowptr[n + 1] - 1;
        d_csrc[pos] = n;
        d_cea[pos]  = d_easum[n] / fmaxf((float)d_cnt[n], 1.f);
    }
}

// ---------------- segment softmax + aggregation ----------------
// out_mode 0: write fp16 to d_x; 1: fused mean-pool (atomicAdd gsum/gcnt).
template <int H>
__global__ __launch_bounds__(256) void agg_kernel(const float* __restrict__ bias,
                           const float* __restrict__ bng, const float* __restrict__ bnb,
                           const float* __restrict__ bnm, const float* __restrict__ bnv,
                           const int* __restrict__ batch,
                           int wd_off, int do_bn, int out_mode) {
    __shared__ float s_pk[8][32][H][2];

    int gw = (blockIdx.x * blockDim.x + threadIdx.x) >> 5;
    if (gw >= NN) return;
    int lane = threadIdx.x & 31;
    int ww = threadIdx.x >> 5;
    int n = gw;
    int beg = d_rowptr[n], end = d_rowptr[n + 1];

    float adh[H], wdv[H];
    #pragma unroll
    for (int h = 0; h < H; h++) { adh[h] = d_adb[n * H + h]; wdv[h] = d_wd[wd_off + h]; }

    float mx[H], sm[H];
    float t0[H], t1[H];
    int src0 = -1, src1 = -1;
    #pragma unroll
    for (int h = 0; h < H; h++) { mx[h] = NEG_BIG; sm[h] = 0.f; }
    {
        int k = 0;
        for (int ec = beg; ec < end; ec += 32, k++) {
            int e = ec + lane;
            float tt[H];
            int ss = -1;
            if (e < end) {
                ss = d_csrc[e];
                float ev = d_cea[e];
                float av[H];
                if constexpr (H == 4) {
                    float4 a4 = *(const float4*)&d_asb[ss * 4];
                    av[0] = a4.x; av[1] = a4.y; av[2] = a4.z; av[3] = a4.w;
                } else {
                    av[0] = d_asb[ss];
                }
                #pragma unroll
                for (int h = 0; h < H; h++) {
                    float t = av[h] + adh[h] + ev * wdv[h];
                    t = t > 0.f ? t : 0.2f * t;
                    tt[h] = t;
                    float mn = fmaxf(mx[h], t);
                    sm[h] = sm[h] * __expf(mx[h] - mn) + __expf(t - mn);
                    mx[h] = mn;
                }
            } else {
                #pragma unroll
                for (int h = 0; h < H; h++) tt[h] = NEG_BIG;
            }
            if (k == 0) {
                src0 = ss;
                #pragma unroll
                for (int h = 0; h < H; h++) t0[h] = tt[h];
            } else if (k == 1) {
                src1 = ss;
                #pragma unroll
                for (int h = 0; h < H; h++) t1[h] = tt[h];
            }
        }
    }
    #pragma unroll
    for (int h = 0; h < H; h++) {
        #pragma unroll
        for (int o = 16; o; o >>= 1) {
            float mo = __shfl_xor_sync(0xffffffffu, mx[h], o);
            float so = __shfl_xor_sync(0xffffffffu, sm[h], o);
            float mn = fmaxf(mx[h], mo);
            sm[h] = sm[h] * __expf(mx[h] - mn) + so * __expf(mo - mn);
            mx[h] = mn;
        }
    }
    __syncwarp();

    constexpr int PL = (H * 64) / 32;
    int hl = (lane * PL) >> 6;
    float acc[PL];
    #pragma unroll
    for (int j = 0; j < PL; j++) acc[j] = 0.f;

    int k2 = 0;
    for (int ec = beg; ec < end; ec += 32, k2++) {
        int e = ec + lane;
        if (e < end) {
            int ss;
            float tt[H];
            if (k2 == 0) {
                ss = src0;
                #pragma unroll
                for (int h = 0; h < H; h++) tt[h] = t0[h];
            } else if (k2 == 1) {
                ss = src1;
                #pragma unroll
                for (int h = 0; h < H; h++) tt[h] = t1[h];
            } else {
                ss = d_csrc[e];
                float ev = d_cea[e];
                float av[H];
                if constexpr (H == 4) {
                    float4 a4 = *(const float4*)&d_asb[ss * 4];
                    av[0] = a4.x; av[1] = a4.y; av[2] = a4.z; av[3] = a4.w;
                } else {
                    av[0] = d_asb[ss];
                }
                #pragma unroll
                for (int h = 0; h < H; h++) {
                    float t = av[h] + adh[h] + ev * wdv[h];
                    tt[h] = t > 0.f ? t : 0.2f * t;
                }
            }
            #pragma unroll
            for (int h = 0; h < H; h++) {
                s_pk[ww][lane][h][0] = __int_as_float(ss);
                s_pk[ww][lane][h][1] = __expf(tt[h] - mx[h]);
            }
        }
        __syncwarp();
        int cnt = min(32, end - ec);
        #pragma unroll 8
        for (int i = 0; i < cnt; i++) {
            float2 p = *(const float2*)&s_pk[ww][i][hl][0];
            int s = __float_as_int(p.x);
            float w = p.y;
            const __half* hr = d_hh + (size_t)s * (H * 64) + lane * PL;
            if constexpr (PL == 8) {
                uint4 raw = *(const uint4*)hr;
                const __half2* hp = (const __half2*)&raw;
                float2 f0 = __half22float2(hp[0]);
                float2 f1 = __half22float2(hp[1]);
                float2 f2 = __half22float2(hp[2]);
                float2 f3 = __half22float2(hp[3]);
                acc[0] = fmaf(w, f0.x, acc[0]); acc[1] = fmaf(w, f0.y, acc[1]);
                acc[2] = fmaf(w, f1.x, acc[2]); acc[3] = fmaf(w, f1.y, acc[3]);
                acc[4] = fmaf(w, f2.x, acc[4]); acc[5] = fmaf(w, f2.y, acc[5]);
                acc[6] = fmaf(w, f3.x, acc[6]); acc[7] = fmaf(w, f3.y, acc[7]);
            } else {
                float2 f = __half22float2(*(const __half2*)hr);
                acc[0] = fmaf(w, f.x, acc[0]);
                acc[1] = fmaf(w, f.y, acc[1]);
            }
        }
        __syncwarp();
    }

    float invl = 1.f / (sm[hl] + 1e-16f);
    if (out_mode == 0) {
        #pragma unroll
        for (int j = 0; j < PL; j++) {
            int c = lane * PL + j;
            float v = acc[j] * invl + bias[c];
            if (do_bn) {
                v = (v - bnm[c]) * rsqrtf(bnv[c] + 1e-5f) * bng[c] + bnb[c];
                v = fmaxf(v, 0.f);
            }
            d_x[(size_t)n * 256 + c] = __float2half_rn(v);
        }
    } else {
        int b = batch[n];
        #pragma unroll
        for (int j = 0; j < PL; j++) {
            int c = lane * PL + j;
            float v = acc[j] * invl + bias[c];
            atomicAdd(&d_gsum[b * 64 + c], v);
        }
        if (lane == 0) atomicAdd(&d_gcnt[b], 1.f);
    }
}

// ---------------- head ----------------
__global__ void head_kernel(const float* __restrict__ cw1, const float* __restrict__ cb1,
                            const float* __restrict__ cw2, const float* __restrict__ cb2,
                            float* __restrict__ out) {
    int g = blockIdx.x, j = threadIdx.x;
    __shared__ float sg[64], sh[64];
    float cntv = fmaxf(d_gcnt[g], 1.f);
    sg[j] = d_gsum[g * 64 + j] / cntv;
    __syncthreads();
    float a = cb1[j];
    #pragma unroll
    for (int k = 0; k < 64; k++) a = fmaf(sg[k], cw1[k * 64 + j], a);
    sh[j] = 0.5f * a * (1.f + erff(a * 0.70710678118654752440f));
    __syncthreads();
    if (j < 2) {
        float o = cb2[j];
        #pragma unroll
        for (int k = 0; k < 64; k++) o = fmaf(sh[k], cw2[k * 2 + j], o);
        out[g * 2 + j] = o;
    }
}

// ---------------- launch ----------------
extern "C" void kernel_launch(void* const* d_in, const int* in_sizes, int n_in,
                              void* d_out, int out_size) {
    (void)in_sizes; (void)n_in; (void)out_size;
    const float* x     = (const float*)d_in[0];
    const int*   ei    = (const int*)  d_in[1];
    const float* ea    = (const float*)d_in[2];
    const int*   batch = (const int*)  d_in[3];
    const float* W0  = (const float*)d_in[4];
    const float* as0 = (const float*)d_in[5];
    const float* ad0 = (const float*)d_in[6];
    const float* We0 = (const float*)d_in[7];
    const float* ae0 = (const float*)d_in[8];
    const float* b0  = (const float*)d_in[9];
    const float* W1  = (const float*)d_in[10];
    const float* as1 = (const float*)d_in[11];
    const float* ad1 = (const float*)d_in[12];
    const float* We1 = (const float*)d_in[13];
    const float* ae1 = (const float*)d_in[14];
    const float* b1  = (const float*)d_in[15];
    const float* W2  = (const float*)d_in[16];
    const float* as2 = (const float*)d_in[17];
    const float* ad2 = (const float*)d_in[18];
    const float* We2 = (const float*)d_in[19];
    const float* ae2 = (const float*)d_in[20];
    const float* b2  = (const float*)d_in[21];
    const float* bng = (const float*)d_in[22];
    const float* bnb = (const float*)d_in[23];
    const float* bnm = (const float*)d_in[24];
    const float* bnv = (const float*)d_in[25];
    const float* cw1 = (const float*)d_in[26];
    const float* cb1 = (const float*)d_in[27];
    const float* cw2 = (const float*)d_in[28];
    const float* cb2 = (const float*)d_in[29];
    float* out = (float*)d_out;

    const int SMEM_G01 = 2 * (128 * 80 + 128 * 80);   // 40960
    const int SMEM_G2  = 2 * (128 * 80 + 64 * 80);    // 30720
    cudaFuncSetAttribute(hmma_gemm<128, 256, KP0, 0, true>,  cudaFuncAttributeMaxDynamicSharedMemorySize, SMEM_G01);
    cudaFuncSetAttribute(hmma_gemm<128, 256, 256, 1, false>, cudaFuncAttributeMaxDynamicSharedMemorySize, SMEM_G01);
    cudaFuncSetAttribute(hmma_gemm<64, 64, 256, 2, false>,   cudaFuncAttributeMaxDynamicSharedMemorySize, SMEM_G2);

    // K1: prep (zero + xsplit + wsplit)
    prep_kernel<<<2048, 256>>>(x, W0, W1, W2);
    // K2: layer-0 GEMM + attn0 + edge count (tail blocks)
    hmma_gemm<128, 256, KP0, 0, true><<<dim3(2, 300), 256, SMEM_G01>>>(ei, ea, as0, ad0);
    // K3: scan + wd
    swa_kernel<<<2, 1024>>>(We0, ae0, We1, ae1, We2, ae2);
    // K4: fill + selfloop
    fillself_kernel<<<900, 256>>>(ei, ea);
    // K5: agg0 (+BN+ReLU)
    agg_kernel<4><<<NN / 8, 256>>>(b0, bng, bnb, bnm, bnv, batch, 0, 1, 0);
    // K6-K7: layer 1 (GEMM+attn1, agg1)
    hmma_gemm<128, 256, 256, 1, false><<<dim3(2, 200), 256, SMEM_G01>>>(ei, ea, as1, ad1);
    agg_kernel<4><<<NN / 8, 256>>>(b1, bng, bnb, bnm, bnv, batch, 4, 1, 0);
    // K8-K9: layer 2 (GEMM+attn2, agg2+pool)
    hmma_gemm<64, 64, 256, 2, false><<<dim3(1, 200), 256, SMEM_G2>>>(ei, ea, as2, ad2);
    agg_kernel<1><<<NN / 8, 256>>>(b2, bng, bnb, bnm, bnv, batch, 8, 0, 1);
    // K10: head
    head_kernel<<<GG, 64>>>(cw1, cb1, cw2, cb2, out);
}

// round 15
// speedup vs baseline: 1.3953x; 1.3953x over previous
#include <cuda_runtime.h>
#include <cuda_fp16.h>
#include <math.h>
#include <stdint.h>

// Problem constants
#define NN   25600
#define EE   409600
#define GG   128
#define INF_ 200
#define HC4  256
#define ETOT (EE + NN)
#define KP0  448            // padded K for layer-0 GEMM (400 -> 448)

#define NEG_BIG (-1.0e30f)

// ---------------- scratch ----------------
__device__ __align__(16) __half d_hh [(size_t)NN * HC4];     // GEMM output (fp16)
__device__ __align__(16) __half d_x  [(size_t)NN * HC4];     // layer 1/2 GEMM A (fp16)
__device__ __align__(16) __half d_a0 [(size_t)NN * KP0];     // layer 0 GEMM A (fp16)
__device__ __align__(16) __half d_b0 [256 * KP0];
__device__ __align__(16) __half d_b1 [256 * 256];
__device__ __align__(16) __half d_b2 [64 * 256];
__device__ __align__(16) float d_asb[NN * 4];
__device__ __align__(16) float d_adb[NN * 4];
__device__ int   d_cnt[NN];
__device__ int   d_fill[NN];
__device__ float d_easum[NN];
__device__ int   d_rowptr[NN + 1];
__device__ int   d_csrc[ETOT];
__device__ float d_cea [ETOT];
__device__ float d_gsum[GG * 64];
__device__ float d_gcnt[GG];
__device__ float d_wd[9];

// ---------------- helpers ----------------
__device__ __forceinline__ uint32_t smem_u32(const void* p) {
    uint32_t a;
    asm("{ .reg .u64 t; cvta.to.shared.u64 t, %1; cvt.u32.u64 %0, t; }" : "=r"(a) : "l"(p));
    return a;
}
__device__ __forceinline__ float warp_sum(float v) {
    #pragma unroll
    for (int o = 16; o; o >>= 1) v += __shfl_xor_sync(0xffffffffu, v, o);
    return v;
}
__device__ __forceinline__ void cp16(uint32_t smem, const void* g) {
    asm volatile("cp.async.cg.shared.global [%0], [%1], 16;" :: "r"(smem), "l"(g) : "memory");
}
__device__ __forceinline__ void ldsm4(uint32_t* r, uint32_t addr) {
    asm volatile("ldmatrix.sync.aligned.m8n8.x4.shared.b16 {%0,%1,%2,%3}, [%4];"
                 : "=r"(r[0]), "=r"(r[1]), "=r"(r[2]), "=r"(r[3]) : "r"(addr));
}
__device__ __forceinline__ void mma16816(float* d, const uint32_t* a, const uint32_t* b) {
    asm volatile("mma.sync.aligned.m16n8k16.row.col.f32.f16.f16.f32 "
                 "{%0,%1,%2,%3}, {%4,%5,%6,%7}, {%8,%9}, {%0,%1,%2,%3};"
                 : "+f"(d[0]), "+f"(d[1]), "+f"(d[2]), "+f"(d[3])
                 : "r"(a[0]), "r"(a[1]), "r"(a[2]), "r"(a[3]), "r"(b[0]), "r"(b[1]));
}

// ---------------- K1: prep = zero + xsplit + wsplit0/1/2 ----------------
__global__ __launch_bounds__(256) void prep_kernel(const float* __restrict__ x,
                                                   const float* __restrict__ W0,
                                                   const float* __restrict__ W1,
                                                   const float* __restrict__ W2) {
    const long ZN = NN;
    const long ZG = GG * 64 + GG;
    const long XS = (long)NN * KP0;
    const long WS0 = 256 * KP0, WS1 = 256 * 256, WS2 = 64 * 256;
    const long total = ZN + ZG + XS + WS0 + WS1 + WS2;
    for (long i = (long)blockIdx.x * blockDim.x + threadIdx.x; i < total;
         i += (long)gridDim.x * blockDim.x) {
        long r = i;
        if (r < ZN) { d_cnt[r] = 0; d_fill[r] = 0; d_easum[r] = 0.f; continue; }
        r -= ZN;
        if (r < ZG) { if (r < GG * 64) d_gsum[r] = 0.f; else d_gcnt[r - GG * 64] = 0.f; continue; }
        r -= ZG;
        if (r < XS) {
            int n = (int)(r / KP0), kk = (int)(r % KP0);
            float v = 0.f;
            if (kk < INF_)        { float t = x[n * INF_ + kk];        v = (t != t) ? 0.f : t; }
            else if (kk < 2*INF_) { float t = x[n * INF_ + kk - INF_]; v = (t != t) ? 1.f : 0.f; }
            d_a0[r] = __float2half_rn(v);
            continue;
        }
        r -= XS;
        if (r < WS0) {
            int n = (int)(r / KP0), k = (int)(r % KP0);
            d_b0[r] = __float2half_rn((k < 400) ? W0[k * 256 + n] : 0.f);
            continue;
        }
        r -= WS0;
        if (r < WS1) {
            int n = (int)(r / 256), k = (int)(r % 256);
            d_b1[r] = __float2half_rn(W1[k * 256 + n]);
            continue;
        }
        r -= WS1;
        {
            int n = (int)(r / 256), k = (int)(r % 256);
            d_b2[r] = __float2half_rn(W2[k * 64 + n]);
        }
    }
}

// ---------------- HMMA fp16 GEMM + phase-separated attn epilogue (+count tail) ----------------
// Phase 1: GEMM, write fp16 C tile. __syncthreads. Phase 2 (acc dead, no reg
// pressure): one thread per (row, head) pair re-reads its 128B row slice from
// d_hh (L2-hit) and dots with att_s/att_d. Block exclusively owns its pairs.
template <int BN, int NSTR, int KPAD, int SEL, bool XCNT>
__global__ __launch_bounds__(256, 2) void hmma_gemm(const int* __restrict__ ei,
                                                    const float* __restrict__ ea,
                                                    const float* __restrict__ att_s,
                                                    const float* __restrict__ att_d) {
    if (XCNT && blockIdx.y >= 200) {
        int cb = (blockIdx.y - 200) * 2 + blockIdx.x;
        for (int e = cb * 256 + threadIdx.x; e < EE; e += 200 * 256) {
            int dd = ei[EE + e];
            float v = ea[e];
            if (v != v) v = 0.f;
            atomicAdd(&d_cnt[dd], 1);
            atomicAdd(&d_easum[dd], v);
        }
        return;
    }

    constexpr int WM = 4;
    constexpr int WN = BN / 32;
    constexpr int PITCH = 80;
    constexpr int ATILE = 128 * PITCH;
    constexpr int BTILE = BN * PITCH;
    constexpr int BUFSZ = ATILE + BTILE;
    constexpr int NCH = KPAD / 32;
    constexpr int ROWB = KPAD * 2;
    constexpr int HLOC = BN / 64;      // heads owned by this block (2 or 1)
    constexpr int HATT = NSTR / 64;    // total heads (4 or 1)

    const __half* Af = (SEL == 0) ? d_a0 : d_x;
    const __half* Bf = (SEL == 0) ? d_b0 : (SEL == 1 ? d_b1 : d_b2);

    extern __shared__ __align__(16) char dsm[];
    uint32_t sb = smem_u32(dsm);

    int tid = threadIdx.x, wid = tid >> 5, lane = tid & 31;
    int m0 = blockIdx.y * 128, n0 = blockIdx.x * BN;
    int mb = (wid >> 2) * 64;
    int nb = (wid & 3) * WN * 8;

    const char* gA = (const char*)Af + (size_t)m0 * ROWB;
    const char* gB = (const char*)Bf + (size_t)n0 * ROWB;

    auto issue = [&](int c, int b) {
        uint32_t base = sb + b * BUFSZ;
        int cb = c * 64;
        #pragma unroll
        for (int i = tid; i < 512; i += 256) {
            int r = i >> 2, u = (i & 3) * 16;
            cp16(base + r * PITCH + u, gA + (size_t)r * ROWB + cb + u);
        }
        #pragma unroll
        for (int i = tid; i < BN * 4; i += 256) {
            int r = i >> 2, u = (i & 3) * 16;
            cp16(base + ATILE + r * PITCH + u, gB + (size_t)r * ROWB + cb + u);
        }
        asm volatile("cp.async.commit_group;" ::: "memory");
    };

    float acc[WM][WN][4];
    #pragma unroll
    for (int i = 0; i < WM; i++)
        #pragma unroll
        for (int j = 0; j < WN; j++)
            #pragma unroll
            for (int q = 0; q < 4; q++) acc[i][j][q] = 0.f;

    uint32_t a_ln = (lane & 15) * PITCH + (lane >> 4) * 16;
    uint32_t b_ln = ((lane & 7) + ((lane >> 4) << 3)) * PITCH + ((lane >> 3) & 1) * 16;

    issue(0, 0);
    for (int c = 0; c < NCH; c++) {
        int buf = c & 1;
        if (c + 1 < NCH) {
            issue(c + 1, buf ^ 1);
            asm volatile("cp.async.wait_group 1;" ::: "memory");
        } else {
            asm volatile("cp.async.wait_group 0;" ::: "memory");
        }
        __syncthreads();

        uint32_t base  = sb + buf * BUFSZ;
        uint32_t a_row = base + mb * PITCH + a_ln;
        uint32_t b_row = base + ATILE + nb * PITCH + b_ln;

        #pragma unroll
        for (int ks = 0; ks < 2; ks++) {
            uint32_t bf[WN / 2][4];
            #pragma unroll
            for (int nt2 = 0; nt2 < WN / 2; nt2++)
                ldsm4(bf[nt2], b_row + nt2 * 16 * PITCH + ks * 32);
            #pragma unroll
            for (int mt = 0; mt < WM; mt++) {
                uint32_t af[4];
                ldsm4(af, a_row + mt * 16 * PITCH + ks * 32);
                #pragma unroll
                for (int nt = 0; nt < WN; nt++)
                    mma16816(acc[mt][nt], af, &bf[nt >> 1][(nt & 1) * 2]);
            }
        }
        __syncthreads();
    }

    // ---- phase 1: write fp16 result (acc dies here) ----
    int r0 = m0 + mb + (lane >> 2);
    int c0 = n0 + nb + (lane & 3) * 2;
    #pragma unroll
    for (int mt = 0; mt < WM; mt++)
        #pragma unroll
        for (int nt = 0; nt < WN; nt++) {
            int rr = r0 + mt * 16, cc = c0 + nt * 8;
            __half2 p01 = __floats2half2_rn(acc[mt][nt][0], acc[mt][nt][1]);
            __half2 p23 = __floats2half2_rn(acc[mt][nt][2], acc[mt][nt][3]);
            *(__half2*)&d_hh[(size_t)rr * NSTR + cc]       = p01;
            *(__half2*)&d_hh[(size_t)(rr + 8) * NSTR + cc] = p23;
        }
    __syncthreads();   // block-wide visibility of this block's d_hh stores

    // ---- phase 2: attn scalars, one thread per (row, head) pair ----
    constexpr int NPAIR = 128 * HLOC;     // 256 (BN=128) or 128 (BN=64)
    if (tid < NPAIR) {
        int row = tid / HLOC, lh = tid % HLOC;
        int gr = m0 + row;
        int hg = (n0 >> 6) + lh;
        const __half2* hp = (const __half2*)(d_hh + (size_t)gr * NSTR + (n0 + lh * 64));
        const float2* sp = (const float2*)(att_s + hg * 64);
        const float2* dp = (const float2*)(att_d + hg * 64);
        float s = 0.f, dd = 0.f;
        #pragma unroll
        for (int j = 0; j < 32; j++) {
            float2 hv = __half22float2(hp[j]);
            float2 sv = sp[j], dv = dp[j];
            s  = fmaf(hv.x, sv.x, fmaf(hv.y, sv.y, s));
            dd = fmaf(hv.x, dv.x, fmaf(hv.y, dv.y, dd));
        }
        d_asb[gr * HATT + hg] = s;
        d_adb[gr * HATT + hg] = dd;
    }
}

// ---------------- K3: scan (block 0) + wd (block 1) ----------------
__global__ __launch_bounds__(1024) void swa_kernel(
    const float* We0, const float* ae0,
    const float* We1, const float* ae1,
    const float* We2, const float* ae2) {
    int tid = threadIdx.x, lane = tid & 31, wid = tid >> 5;

    if (blockIdx.x == 0) {
        __shared__ int wsum[32];
        __shared__ int s_off;
        if (tid == 0) { d_rowptr[0] = 0; s_off = 0; }
        __syncthreads();
        for (int base = 0; base < NN; base += 1024) {
            int inc = d_cnt[base + tid] + 1;
            #pragma unroll
            for (int o = 1; o < 32; o <<= 1) {
                int t = __shfl_up_sync(0xffffffffu, inc, o);
                if (lane >= o) inc += t;
            }
            if (lane == 31) wsum[wid] = inc;
            __syncthreads();
            if (wid == 0) {
                int wi = wsum[lane];
                #pragma unroll
                for (int o = 1; o < 32; o <<= 1) {
                    int t = __shfl_up_sync(0xffffffffu, wi, o);
                    if (lane >= o) wi += t;
                }
                wsum[lane] = wi;
            }
            __syncthreads();
            int excl_w = wid ? wsum[wid - 1] : 0;
            d_rowptr[base + tid + 1] = s_off + excl_w + inc;
            __syncthreads();
            if (tid == 0) s_off += wsum[31];
            __syncthreads();
        }
        return;
    }
    // we_dot
    if (wid >= 9) return;
    const float *We, *ae; int h;
    if (wid < 4)      { We = We0; ae = ae0; h = wid; }
    else if (wid < 8) { We = We1; ae = ae1; h = wid - 4; }
    else              { We = We2; ae = ae2; h = 0; }
    float s = 0.f;
    for (int c = lane; c < 64; c += 32) s += We[h * 64 + c] * ae[h * 64 + c];
    s = warp_sum(s);
    if (lane == 0) d_wd[wid] = s;
}

// ---------------- K4: fill (blocks 0..799) + selfloop (blocks 800..899) ----------------
__global__ __launch_bounds__(256) void fillself_kernel(const int* __restrict__ ei,
                                                       const float* __restrict__ ea) {
    int b = blockIdx.x;
    if (b < 800) {
        for (int e = b * 256 + threadIdx.x; e < EE; e += 800 * 256) {
            int s = ei[e], d = ei[EE + e];
            float v = ea[e];
            if (v != v) v = 0.f;
            int pos = d_rowptr[d] + atomicAdd(&d_fill[d], 1);
            d_csrc[pos] = s;
            d_cea[pos]  = v;
        }
    } else {
        int n = (b - 800) * 256 + threadIdx.x;
        if (n >= NN) return;
        int pos = d_rowptr[n + 1] - 1;
        d_csrc[pos] = n;
        d_cea[pos]  = d_easum[n] / fmaxf((float)d_cnt[n], 1.f);
    }
}

// ---------------- segment softmax + aggregation ----------------
// out_mode 0: write fp16 to d_x; 1: fused mean-pool (atomicAdd gsum/gcnt).
template <int H>
__global__ __launch_bounds__(256) void agg_kernel(const float* __restrict__ bias,
                           const float* __restrict__ bng, const float* __restrict__ bnb,
                           const float* __restrict__ bnm, const float* __restrict__ bnv,
                           const int* __restrict__ batch,
                           int wd_off, int do_bn, int out_mode) {
    __shared__ float s_pk[8][32][H][2];

    int gw = (blockIdx.x * blockDim.x + threadIdx.x) >> 5;
    if (gw >= NN) return;
    int lane = threadIdx.x & 31;
    int ww = threadIdx.x >> 5;
    int n = gw;
    int beg = d_rowptr[n], end = d_rowptr[n + 1];

    float adh[H], wdv[H];
    #pragma unroll
    for (int h = 0; h < H; h++) { adh[h] = d_adb[n * H + h]; wdv[h] = d_wd[wd_off + h]; }

    float mx[H], sm[H];
    float t0[H], t1[H];
    int src0 = -1, src1 = -1;
    #pragma unroll
    for (int h = 0; h < H; h++) { mx[h] = NEG_BIG; sm[h] = 0.f; }
    {
        int k = 0;
        for (int ec = beg; ec < end; ec += 32, k++) {
            int e = ec + lane;
            float tt[H];
            int ss = -1;
            if (e < end) {
                ss = d_csrc[e];
                float ev = d_cea[e];
                float av[H];
                if constexpr (H == 4) {
                    float4 a4 = *(const float4*)&d_asb[ss * 4];
                    av[0] = a4.x; av[1] = a4.y; av[2] = a4.z; av[3] = a4.w;
                } else {
                    av[0] = d_asb[ss];
                }
                #pragma unroll
                for (int h = 0; h < H; h++) {
                    float t = av[h] + adh[h] + ev * wdv[h];
                    t = t > 0.f ? t : 0.2f * t;
                    tt[h] = t;
                    float mn = fmaxf(mx[h], t);
                    sm[h] = sm[h] * __expf(mx[h] - mn) + __expf(t - mn);
                    mx[h] = mn;
                }
            } else {
                #pragma unroll
                for (int h = 0; h < H; h++) tt[h] = NEG_BIG;
            }
            if (k == 0) {
                src0 = ss;
                #pragma unroll
                for (int h = 0; h < H; h++) t0[h] = tt[h];
            } else if (k == 1) {
                src1 = ss;
                #pragma unroll
                for (int h = 0; h < H; h++) t1[h] = tt[h];
            }
        }
    }
    #pragma unroll
    for (int h = 0; h < H; h++) {
        #pragma unroll
        for (int o = 16; o; o >>= 1) {
            float mo = __shfl_xor_sync(0xffffffffu, mx[h], o);
            float so = __shfl_xor_sync(0xffffffffu, sm[h], o);
            float mn = fmaxf(mx[h], mo);
            sm[h] = sm[h] * __expf(mx[h] - mn) + so * __expf(mo - mn);
            mx[h] = mn;
        }
    }
    __syncwarp();

    constexpr int PL = (H * 64) / 32;
    int hl = (lane * PL) >> 6;
    float acc[PL];
    #pragma unroll
    for (int j = 0; j < PL; j++) acc[j] = 0.f;

    int k2 = 0;
    for (int ec = beg; ec < end; ec += 32, k2++) {
        int e = ec + lane;
        if (e < end) {
            int ss;
            float tt[H];
            if (k2 == 0) {
                ss = src0;
                #pragma unroll
                for (int h = 0; h < H; h++) tt[h] = t0[h];
            } else if (k2 == 1) {
                ss = src1;
                #pragma unroll
                for (int h = 0; h < H; h++) tt[h] = t1[h];
            } else {
                ss = d_csrc[e];
                float ev = d_cea[e];
                float av[H];
                if constexpr (H == 4) {
                    float4 a4 = *(const float4*)&d_asb[ss * 4];
                    av[0] = a4.x; av[1] = a4.y; av[2] = a4.z; av[3] = a4.w;
                } else {
                    av[0] = d_asb[ss];
                }
                #pragma unroll
                for (int h = 0; h < H; h++) {
                    float t = av[h] + adh[h] + ev * wdv[h];
                    tt[h] = t > 0.f ? t : 0.2f * t;
                }
            }
            #pragma unroll
            for (int h = 0; h < H; h++) {
                s_pk[ww][lane][h][0] = __int_as_float(ss);
                s_pk[ww][lane][h][1] = __expf(tt[h] - mx[h]);
            }
        }
        __syncwarp();
        int cnt = min(32, end - ec);
        #pragma unroll 8
        for (int i = 0; i < cnt; i++) {
            float2 p = *(const float2*)&s_pk[ww][i][hl][0];
            int s = __float_as_int(p.x);
            float w = p.y;
            const __half* hr = d_hh + (size_t)s * (H * 64) + lane * PL;
            if constexpr (PL == 8) {
                uint4 raw = *(const uint4*)hr;
                const __half2* hp = (const __half2*)&raw;
                float2 f0 = __half22float2(hp[0]);
                float2 f1 = __half22float2(hp[1]);
                float2 f2 = __half22float2(hp[2]);
                float2 f3 = __half22float2(hp[3]);
                acc[0] = fmaf(w, f0.x, acc[0]); acc[1] = fmaf(w, f0.y, acc[1]);
                acc[2] = fmaf(w, f1.x, acc[2]); acc[3] = fmaf(w, f1.y, acc[3]);
                acc[4] = fmaf(w, f2.x, acc[4]); acc[5] = fmaf(w, f2.y, acc[5]);
                acc[6] = fmaf(w, f3.x, acc[6]); acc[7] = fmaf(w, f3.y, acc[7]);
            } else {
                float2 f = __half22float2(*(const __half2*)hr);
                acc[0] = fmaf(w, f.x, acc[0]);
                acc[1] = fmaf(w, f.y, acc[1]);
            }
        }
        __syncwarp();
    }

    float invl = 1.f / (sm[hl] + 1e-16f);
    if (out_mode == 0) {
        #pragma unroll
        for (int j = 0; j < PL; j++) {
            int c = lane * PL + j;
            float v = acc[j] * invl + bias[c];
            if (do_bn) {
                v = (v - bnm[c]) * rsqrtf(bnv[c] + 1e-5f) * bng[c] + bnb[c];
                v = fmaxf(v, 0.f);
            }
            d_x[(size_t)n * 256 + c] = __float2half_rn(v);
        }
    } else {
        int b = batch[n];
        #pragma unroll
        for (int j = 0; j < PL; j++) {
            int c = lane * PL + j;
            float v = acc[j] * invl + bias[c];
            atomicAdd(&d_gsum[b * 64 + c], v);
        }
        if (lane == 0) atomicAdd(&d_gcnt[b], 1.f);
    }
}

// ---------------- head ----------------
__global__ void head_kernel(const float* __restrict__ cw1, const float* __restrict__ cb1,
                            const float* __restrict__ cw2, const float* __restrict__ cb2,
                            float* __restrict__ out) {
    int g = blockIdx.x, j = threadIdx.x;
    __shared__ float sg[64], sh[64];
    float cntv = fmaxf(d_gcnt[g], 1.f);
    sg[j] = d_gsum[g * 64 + j] / cntv;
    __syncthreads();
    float a = cb1[j];
    #pragma unroll
    for (int k = 0; k < 64; k++) a = fmaf(sg[k], cw1[k * 64 + j], a);
    sh[j] = 0.5f * a * (1.f + erff(a * 0.70710678118654752440f));
    __syncthreads();
    if (j < 2) {
        float o = cb2[j];
        #pragma unroll
        for (int k = 0; k < 64; k++) o = fmaf(sh[k], cw2[k * 2 + j], o);
        out[g * 2 + j] = o;
    }
}

// ---------------- launch ----------------
extern "C" void kernel_launch(void* const* d_in, const int* in_sizes, int n_in,
                              void* d_out, int out_size) {
    (void)in_sizes; (void)n_in; (void)out_size;
    const float* x     = (const float*)d_in[0];
    const int*   ei    = (const int*)  d_in[1];
    const float* ea    = (const float*)d_in[2];
    const int*   batch = (const int*)  d_in[3];
    const float* W0  = (const float*)d_in[4];
    const float* as0 = (const float*)d_in[5];
    const float* ad0 = (const float*)d_in[6];
    const float* We0 = (const float*)d_in[7];
    const float* ae0 = (const float*)d_in[8];
    const float* b0  = (const float*)d_in[9];
    const float* W1  = (const float*)d_in[10];
    const float* as1 = (const float*)d_in[11];
    const float* ad1 = (const float*)d_in[12];
    const float* We1 = (const float*)d_in[13];
    const float* ae1 = (const float*)d_in[14];
    const float* b1  = (const float*)d_in[15];
    const float* W2  = (const float*)d_in[16];
    const float* as2 = (const float*)d_in[17];
    const float* ad2 = (const float*)d_in[18];
    const float* We2 = (const float*)d_in[19];
    const float* ae2 = (const float*)d_in[20];
    const float* b2  = (const float*)d_in[21];
    const float* bng = (const float*)d_in[22];
    const float* bnb = (const float*)d_in[23];
    const float* bnm = (const float*)d_in[24];
    const float* bnv = (const float*)d_in[25];
    const float* cw1 = (const float*)d_in[26];
    const float* cb1 = (const float*)d_in[27];
    const float* cw2 = (const float*)d_in[28];
    const float* cb2 = (const float*)d_in[29];
    float* out = (float*)d_out;

    const int SMEM_G01 = 2 * (128 * 80 + 128 * 80);   // 40960
    const int SMEM_G2  = 2 * (128 * 80 + 64 * 80);    // 30720
    cudaFuncSetAttribute(hmma_gemm<128, 256, KP0, 0, true>,  cudaFuncAttributeMaxDynamicSharedMemorySize, SMEM_G01);
    cudaFuncSetAttribute(hmma_gemm<128, 256, 256, 1, false>, cudaFuncAttributeMaxDynamicSharedMemorySize, SMEM_G01);
    cudaFuncSetAttribute(hmma_gemm<64, 64, 256, 2, false>,   cudaFuncAttributeMaxDynamicSharedMemorySize, SMEM_G2);

    // K1: prep (zero + xsplit + wsplit)
    prep_kernel<<<2048, 256>>>(x, W0, W1, W2);
    // K2: layer-0 GEMM + attn0 (phase-2 epilogue) + edge count (tail blocks)
    hmma_gemm<128, 256, KP0, 0, true><<<dim3(2, 300), 256, SMEM_G01>>>(ei, ea, as0, ad0);
    // K3: scan + wd
    swa_kernel<<<2, 1024>>>(We0, ae0, We1, ae1, We2, ae2);
    // K4: fill + selfloop
    fillself_kernel<<<900, 256>>>(ei, ea);
    // K5: agg0 (+BN+ReLU)
    agg_kernel<4><<<NN / 8, 256>>>(b0, bng, bnb, bnm, bnv, batch, 0, 1, 0);
    // K6-K7: layer 1 (GEMM+attn1, agg1)
    hmma_gemm<128, 256, 256, 1, false><<<dim3(2, 200), 256, SMEM_G01>>>(ei, ea, as1, ad1);
    agg_kernel<4><<<NN / 8, 256>>>(b1, bng, bnb, bnm, bnv, batch, 4, 1, 0);
    // K8-K9: layer 2 (GEMM+attn2, agg2+pool)
    hmma_gemm<64, 64, 256, 2, false><<<dim3(1, 200), 256, SMEM_G2>>>(ei, ea, as2, ad2);
    agg_kernel<1><<<NN / 8, 256>>>(b2, bng, bnb, bnm, bnv, batch, 8, 0, 1);
    // K10: head
    head_kernel<<<GG, 64>>>(cw1, cb1, cw2, cb2, out);
}

// round 16
// speedup vs baseline: 1.4450x; 1.0356x over previous
#include <cuda_runtime.h>
#include <cuda_fp16.h>
#include <math.h>
#include <stdint.h>

// Problem constants
#define NN   25600
#define EE   409600
#define GG   128
#define INF_ 200
#define HC4  256
#define ETOT (EE + NN)
#define KP0  416            // padded K for layer-0 GEMM (400 -> 416, 13 chunks of 32)

#define NEG_BIG (-1.0e30f)

// ---------------- scratch ----------------
__device__ __align__(16) __half d_hh [(size_t)NN * HC4];     // GEMM output (fp16)
__device__ __align__(16) __half d_x  [(size_t)NN * HC4];     // layer 1/2 GEMM A (fp16)
__device__ __align__(16) __half d_a0 [(size_t)NN * KP0];     // layer 0 GEMM A (fp16)
__device__ __align__(16) __half d_b0 [256 * KP0];
__device__ __align__(16) __half d_b1 [256 * 256];
__device__ __align__(16) __half d_b2 [64 * 256];
__device__ __align__(16) float d_asb[NN * 4];
__device__ __align__(16) float d_adb[NN * 4];
__device__ int   d_cnt[NN];
__device__ int   d_fill[NN];
__device__ float d_easum[NN];
__device__ int   d_rowptr[NN + 1];
__device__ int   d_csrc[ETOT];
__device__ float d_cea [ETOT];
__device__ float d_gsum[GG * 64];
__device__ float d_gcnt[GG];
__device__ float d_wd[9];

// ---------------- helpers ----------------
__device__ __forceinline__ uint32_t smem_u32(const void* p) {
    uint32_t a;
    asm("{ .reg .u64 t; cvta.to.shared.u64 t, %1; cvt.u32.u64 %0, t; }" : "=r"(a) : "l"(p));
    return a;
}
__device__ __forceinline__ float warp_sum(float v) {
    #pragma unroll
    for (int o = 16; o; o >>= 1) v += __shfl_xor_sync(0xffffffffu, v, o);
    return v;
}
__device__ __forceinline__ void cp16(uint32_t smem, const void* g) {
    asm volatile("cp.async.cg.shared.global [%0], [%1], 16;" :: "r"(smem), "l"(g) : "memory");
}
__device__ __forceinline__ void ldsm4(uint32_t* r, uint32_t addr) {
    asm volatile("ldmatrix.sync.aligned.m8n8.x4.shared.b16 {%0,%1,%2,%3}, [%4];"
                 : "=r"(r[0]), "=r"(r[1]), "=r"(r[2]), "=r"(r[3]) : "r"(addr));
}
__device__ __forceinline__ void mma16816(float* d, const uint32_t* a, const uint32_t* b) {
    asm volatile("mma.sync.aligned.m16n8k16.row.col.f32.f16.f16.f32 "
                 "{%0,%1,%2,%3}, {%4,%5,%6,%7}, {%8,%9}, {%0,%1,%2,%3};"
                 : "+f"(d[0]), "+f"(d[1]), "+f"(d[2]), "+f"(d[3])
                 : "r"(a[0]), "r"(a[1]), "r"(a[2]), "r"(a[3]), "r"(b[0]), "r"(b[1]));
}

// ---------------- K1: prep = zero + xsplit + wsplit0/1/2 ----------------
__global__ __launch_bounds__(256) void prep_kernel(const float* __restrict__ x,
                                                   const float* __restrict__ W0,
                                                   const float* __restrict__ W1,
                                                   const float* __restrict__ W2) {
    const long ZN = NN;
    const long ZG = GG * 64 + GG;
    const long XS = (long)NN * KP0;
    const long WS0 = 256 * KP0, WS1 = 256 * 256, WS2 = 64 * 256;
    const long total = ZN + ZG + XS + WS0 + WS1 + WS2;
    for (long i = (long)blockIdx.x * blockDim.x + threadIdx.x; i < total;
         i += (long)gridDim.x * blockDim.x) {
        long r = i;
        if (r < ZN) { d_cnt[r] = 0; d_fill[r] = 0; d_easum[r] = 0.f; continue; }
        r -= ZN;
        if (r < ZG) { if (r < GG * 64) d_gsum[r] = 0.f; else d_gcnt[r - GG * 64] = 0.f; continue; }
        r -= ZG;
        if (r < XS) {
            int n = (int)(r / KP0), kk = (int)(r % KP0);
            float v = 0.f;
            if (kk < INF_)        { float t = x[n * INF_ + kk];        v = (t != t) ? 0.f : t; }
            else if (kk < 2*INF_) { float t = x[n * INF_ + kk - INF_]; v = (t != t) ? 1.f : 0.f; }
            d_a0[r] = __float2half_rn(v);
            continue;
        }
        r -= XS;
        if (r < WS0) {
            int n = (int)(r / KP0), k = (int)(r % KP0);
            d_b0[r] = __float2half_rn((k < 400) ? W0[k * 256 + n] : 0.f);
            continue;
        }
        r -= WS0;
        if (r < WS1) {
            int n = (int)(r / 256), k = (int)(r % 256);
            d_b1[r] = __float2half_rn(W1[k * 256 + n]);
            continue;
        }
        r -= WS1;
        {
            int n = (int)(r / 256), k = (int)(r % 256);
            d_b2[r] = __float2half_rn(W2[k * 64 + n]);
        }
    }
}

// ---------------- HMMA fp16 GEMM (+optional edge-count tail blocks) ----------------
template <int BN, int NSTR, int KPAD, int SEL, bool XCNT>
__global__ __launch_bounds__(256, 2) void hmma_gemm(const int* __restrict__ ei,
                                                    const float* __restrict__ ea) {
    if (XCNT && blockIdx.y >= 200) {
        int cb = (blockIdx.y - 200) * 2 + blockIdx.x;
        for (int e = cb * 256 + threadIdx.x; e < EE; e += 200 * 256) {
            int dd = ei[EE + e];
            float v = ea[e];
            if (v != v) v = 0.f;
            atomicAdd(&d_cnt[dd], 1);
            atomicAdd(&d_easum[dd], v);
        }
        return;
    }

    constexpr int WM = 4;
    constexpr int WN = BN / 32;
    constexpr int PITCH = 80;
    constexpr int ATILE = 128 * PITCH;
    constexpr int BTILE = BN * PITCH;
    constexpr int BUFSZ = ATILE + BTILE;
    constexpr int NCH = KPAD / 32;
    constexpr int ROWB = KPAD * 2;

    const __half* Af = (SEL == 0) ? d_a0 : d_x;
    const __half* Bf = (SEL == 0) ? d_b0 : (SEL == 1 ? d_b1 : d_b2);

    extern __shared__ __align__(16) char dsm[];
    uint32_t sb = smem_u32(dsm);

    int tid = threadIdx.x, wid = tid >> 5, lane = tid & 31;
    int m0 = blockIdx.y * 128, n0 = blockIdx.x * BN;
    int mb = (wid >> 2) * 64;
    int nb = (wid & 3) * WN * 8;

    const char* gA = (const char*)Af + (size_t)m0 * ROWB;
    const char* gB = (const char*)Bf + (size_t)n0 * ROWB;

    auto issue = [&](int c, int b) {
        uint32_t base = sb + b * BUFSZ;
        int cb = c * 64;
        #pragma unroll
        for (int i = tid; i < 512; i += 256) {
            int r = i >> 2, u = (i & 3) * 16;
            cp16(base + r * PITCH + u, gA + (size_t)r * ROWB + cb + u);
        }
        #pragma unroll
        for (int i = tid; i < BN * 4; i += 256) {
            int r = i >> 2, u = (i & 3) * 16;
            cp16(base + ATILE + r * PITCH + u, gB + (size_t)r * ROWB + cb + u);
        }
        asm volatile("cp.async.commit_group;" ::: "memory");
    };

    float acc[WM][WN][4];
    #pragma unroll
    for (int i = 0; i < WM; i++)
        #pragma unroll
        for (int j = 0; j < WN; j++)
            #pragma unroll
            for (int q = 0; q < 4; q++) acc[i][j][q] = 0.f;

    uint32_t a_ln = (lane & 15) * PITCH + (lane >> 4) * 16;
    uint32_t b_ln = ((lane & 7) + ((lane >> 4) << 3)) * PITCH + ((lane >> 3) & 1) * 16;

    issue(0, 0);
    for (int c = 0; c < NCH; c++) {
        int buf = c & 1;
        if (c + 1 < NCH) {
            issue(c + 1, buf ^ 1);
            asm volatile("cp.async.wait_group 1;" ::: "memory");
        } else {
            asm volatile("cp.async.wait_group 0;" ::: "memory");
        }
        __syncthreads();

        uint32_t base  = sb + buf * BUFSZ;
        uint32_t a_row = base + mb * PITCH + a_ln;
        uint32_t b_row = base + ATILE + nb * PITCH + b_ln;

        #pragma unroll
        for (int ks = 0; ks < 2; ks++) {
            uint32_t bf[WN / 2][4];
            #pragma unroll
            for (int nt2 = 0; nt2 < WN / 2; nt2++)
                ldsm4(bf[nt2], b_row + nt2 * 16 * PITCH + ks * 32);
            #pragma unroll
            for (int mt = 0; mt < WM; mt++) {
                uint32_t af[4];
                ldsm4(af, a_row + mt * 16 * PITCH + ks * 32);
                #pragma unroll
                for (int nt = 0; nt < WN; nt++)
                    mma16816(acc[mt][nt], af, &bf[nt >> 1][(nt & 1) * 2]);
            }
        }
        __syncthreads();
    }

    int r0 = m0 + mb + (lane >> 2);
    int c0 = n0 + nb + (lane & 3) * 2;
    #pragma unroll
    for (int mt = 0; mt < WM; mt++)
        #pragma unroll
        for (int nt = 0; nt < WN; nt++) {
            int rr = r0 + mt * 16, cc = c0 + nt * 8;
            __half2 p01 = __floats2half2_rn(acc[mt][nt][0], acc[mt][nt][1]);
            __half2 p23 = __floats2half2_rn(acc[mt][nt][2], acc[mt][nt][3]);
            *(__half2*)&d_hh[(size_t)rr * NSTR + cc]       = p01;
            *(__half2*)&d_hh[(size_t)(rr + 8) * NSTR + cc] = p23;
        }
}

// ---------------- K3: scan (block 0) + wd (block 1) + attn0 (blocks 2..) ----------------
__global__ __launch_bounds__(1024) void swa_kernel(
    const float* __restrict__ as0, const float* __restrict__ ad0,
    const float* We0, const float* ae0,
    const float* We1, const float* ae1,
    const float* We2, const float* ae2) {
    int tid = threadIdx.x, lane = tid & 31, wid = tid >> 5;

    if (blockIdx.x == 0) {
        __shared__ int wsum[32];
        __shared__ int s_off;
        if (tid == 0) { d_rowptr[0] = 0; s_off = 0; }
        __syncthreads();
        for (int base = 0; base < NN; base += 1024) {
            int inc = d_cnt[base + tid] + 1;
            #pragma unroll
            for (int o = 1; o < 32; o <<= 1) {
                int t = __shfl_up_sync(0xffffffffu, inc, o);
                if (lane >= o) inc += t;
            }
            if (lane == 31) wsum[wid] = inc;
            __syncthreads();
            if (wid == 0) {
                int wi = wsum[lane];
                #pragma unroll
                for (int o = 1; o < 32; o <<= 1) {
                    int t = __shfl_up_sync(0xffffffffu, wi, o);
                    if (lane >= o) wi += t;
                }
                wsum[lane] = wi;
            }
            __syncthreads();
            int excl_w = wid ? wsum[wid - 1] : 0;
            d_rowptr[base + tid + 1] = s_off + excl_w + inc;
            __syncthreads();
            if (tid == 0) s_off += wsum[31];
            __syncthreads();
        }
        return;
    }
    if (blockIdx.x == 1) {
        if (wid >= 9) return;
        const float *We, *ae; int h;
        if (wid < 4)      { We = We0; ae = ae0; h = wid; }
        else if (wid < 8) { We = We1; ae = ae1; h = wid - 4; }
        else              { We = We2; ae = ae2; h = 0; }
        float s = 0.f;
        for (int c = lane; c < 64; c += 32) s += We[h * 64 + c] * ae[h * 64 + c];
        s = warp_sum(s);
        if (lane == 0) d_wd[wid] = s;
        return;
    }
    // attn0: 32 warps = 8 nodes x 4 heads
    int n = (blockIdx.x - 2) * 8 + (wid >> 2);
    int h = wid & 3;
    const __half2* hr = (const __half2*)(d_hh + (size_t)n * 256 + h * 64);
    const float2* asv = (const float2*)(as0 + h * 64);
    const float2* adv = (const float2*)(ad0 + h * 64);
    float2 hv = __half22float2(hr[lane]);
    float2 sv = asv[lane], dv = adv[lane];
    float s  = hv.x * sv.x + hv.y * sv.y;
    float dd = hv.x * dv.x + hv.y * dv.y;
    s = warp_sum(s); dd = warp_sum(dd);
    if (lane == 0) { d_asb[n * 4 + h] = s; d_adb[n * 4 + h] = dd; }
}

// ---------------- K4: fill (blocks 0..1599) + selfloop (blocks 1600..1699) ----------------
__global__ __launch_bounds__(256) void fillself_kernel(const int* __restrict__ ei,
                                                       const float* __restrict__ ea) {
    int b = blockIdx.x;
    if (b < 1600) {
        int e = b * 256 + threadIdx.x;
        if (e < EE) {
            int s = ei[e], d = ei[EE + e];
            float v = ea[e];
            if (v != v) v = 0.f;
            int pos = d_rowptr[d] + atomicAdd(&d_fill[d], 1);
            d_csrc[pos] = s;
            d_cea[pos]  = v;
        }
    } else {
        int n = (b - 1600) * 256 + threadIdx.x;
        if (n >= NN) return;
        int pos = d_rowptr[n + 1] - 1;
        d_csrc[pos] = n;
        d_cea[pos]  = d_easum[n] / fmaxf((float)d_cnt[n], 1.f);
    }
}

// ---------------- per-node attention scalars (layers 1, 2) ----------------
template <int H>
__global__ __launch_bounds__(256) void attn_kernel(const float* __restrict__ att_s,
                                                   const float* __restrict__ att_d) {
    constexpr int NPB = 8 / H;
    int tid = threadIdx.x, wid = tid >> 5, lane = tid & 31;
    int n = blockIdx.x * NPB + wid / H;
    int h = wid % H;
    const __half2* hr = (const __half2*)(d_hh + (size_t)n * (H * 64) + h * 64);
    const float2* asv = (const float2*)(att_s + h * 64);
    const float2* adv = (const float2*)(att_d + h * 64);
    float2 hv = __half22float2(hr[lane]);
    float2 sv = asv[lane], dv = adv[lane];
    float s  = hv.x * sv.x + hv.y * sv.y;
    float dd = hv.x * dv.x + hv.y * dv.y;
    s = warp_sum(s); dd = warp_sum(dd);
    if (lane == 0) { d_asb[n * H + h] = s; d_adb[n * H + h] = dd; }
}

// ---------------- segment softmax + aggregation ----------------
// out_mode 0: write fp16 to d_x; 1: fused mean-pool (atomicAdd gsum/gcnt).
template <int H>
__global__ __launch_bounds__(256) void agg_kernel(const float* __restrict__ bias,
                           const float* __restrict__ bng, const float* __restrict__ bnb,
                           const float* __restrict__ bnm, const float* __restrict__ bnv,
                           const int* __restrict__ batch,
                           int wd_off, int do_bn, int out_mode) {
    __shared__ float s_pk[8][32][H][2];

    int gw = (blockIdx.x * blockDim.x + threadIdx.x) >> 5;
    if (gw >= NN) return;
    int lane = threadIdx.x & 31;
    int ww = threadIdx.x >> 5;
    int n = gw;
    int beg = d_rowptr[n], end = d_rowptr[n + 1];

    float adh[H], wdv[H];
    #pragma unroll
    for (int h = 0; h < H; h++) { adh[h] = d_adb[n * H + h]; wdv[h] = d_wd[wd_off + h]; }

    float mx[H], sm[H];
    float t0[H], t1[H];
    int src0 = -1, src1 = -1;
    #pragma unroll
    for (int h = 0; h < H; h++) { mx[h] = NEG_BIG; sm[h] = 0.f; }
    {
        int k = 0;
        for (int ec = beg; ec < end; ec += 32, k++) {
            int e = ec + lane;
            float tt[H];
            int ss = -1;
            if (e < end) {
                ss = d_csrc[e];
                float ev = d_cea[e];
                float av[H];
                if constexpr (H == 4) {
                    float4 a4 = *(const float4*)&d_asb[ss * 4];
                    av[0] = a4.x; av[1] = a4.y; av[2] = a4.z; av[3] = a4.w;
                } else {
                    av[0] = d_asb[ss];
                }
                #pragma unroll
                for (int h = 0; h < H; h++) {
                    float t = av[h] + adh[h] + ev * wdv[h];
                    t = t > 0.f ? t : 0.2f * t;
                    tt[h] = t;
                    float mn = fmaxf(mx[h], t);
                    sm[h] = sm[h] * __expf(mx[h] - mn) + __expf(t - mn);
                    mx[h] = mn;
                }
            } else {
                #pragma unroll
                for (int h = 0; h < H; h++) tt[h] = NEG_BIG;
            }
            if (k == 0) {
                src0 = ss;
                #pragma unroll
                for (int h = 0; h < H; h++) t0[h] = tt[h];
            } else if (k == 1) {
                src1 = ss;
                #pragma unroll
                for (int h = 0; h < H; h++) t1[h] = tt[h];
            }
        }
    }
    #pragma unroll
    for (int h = 0; h < H; h++) {
        #pragma unroll
        for (int o = 16; o; o >>= 1) {
            float mo = __shfl_xor_sync(0xffffffffu, mx[h], o);
            float so = __shfl_xor_sync(0xffffffffu, sm[h], o);
            float mn = fmaxf(mx[h], mo);
            sm[h] = sm[h] * __expf(mx[h] - mn) + so * __expf(mo - mn);
            mx[h] = mn;
        }
    }
    __syncwarp();

    constexpr int PL = (H * 64) / 32;
    int hl = (lane * PL) >> 6;
    float acc[PL];
    #pragma unroll
    for (int j = 0; j < PL; j++) acc[j] = 0.f;

    int k2 = 0;
    for (int ec = beg; ec < end; ec += 32, k2++) {
        int e = ec + lane;
        if (e < end) {
            int ss;
            float tt[H];
            if (k2 == 0) {
                ss = src0;
                #pragma unroll
                for (int h = 0; h < H; h++) tt[h] = t0[h];
            } else if (k2 == 1) {
                ss = src1;
                #pragma unroll
                for (int h = 0; h < H; h++) tt[h] = t1[h];
            } else {
                ss = d_csrc[e];
                float ev = d_cea[e];
                float av[H];
                if constexpr (H == 4) {
                    float4 a4 = *(const float4*)&d_asb[ss * 4];
                    av[0] = a4.x; av[1] = a4.y; av[2] = a4.z; av[3] = a4.w;
                } else {
                    av[0] = d_asb[ss];
                }
                #pragma unroll
                for (int h = 0; h < H; h++) {
                    float t = av[h] + adh[h] + ev * wdv[h];
                    tt[h] = t > 0.f ? t : 0.2f * t;
                }
            }
            #pragma unroll
            for (int h = 0; h < H; h++) {
                s_pk[ww][lane][h][0] = __int_as_float(ss);
                s_pk[ww][lane][h][1] = __expf(tt[h] - mx[h]);
            }
        }
        __syncwarp();
        int cnt = min(32, end - ec);
        #pragma unroll 8
        for (int i = 0; i < cnt; i++) {
            float2 p = *(const float2*)&s_pk[ww][i][hl][0];
            int s = __float_as_int(p.x);
            float w = p.y;
            const __half* hr = d_hh + (size_t)s * (H * 64) + lane * PL;
            if constexpr (PL == 8) {
                uint4 raw = *(const uint4*)hr;
                const __half2* hp = (const __half2*)&raw;
                float2 f0 = __half22float2(hp[0]);
                float2 f1 = __half22float2(hp[1]);
                float2 f2 = __half22float2(hp[2]);
                float2 f3 = __half22float2(hp[3]);
                acc[0] = fmaf(w, f0.x, acc[0]); acc[1] = fmaf(w, f0.y, acc[1]);
                acc[2] = fmaf(w, f1.x, acc[2]); acc[3] = fmaf(w, f1.y, acc[3]);
                acc[4] = fmaf(w, f2.x, acc[4]); acc[5] = fmaf(w, f2.y, acc[5]);
                acc[6] = fmaf(w, f3.x, acc[6]); acc[7] = fmaf(w, f3.y, acc[7]);
            } else {
                float2 f = __half22float2(*(const __half2*)hr);
                acc[0] = fmaf(w, f.x, acc[0]);
                acc[1] = fmaf(w, f.y, acc[1]);
            }
        }
        __syncwarp();
    }

    float invl = 1.f / (sm[hl] + 1e-16f);
    if (out_mode == 0) {
        #pragma unroll
        for (int j = 0; j < PL; j++) {
            int c = lane * PL + j;
            float v = acc[j] * invl + bias[c];
            if (do_bn) {
                v = (v - bnm[c]) * rsqrtf(bnv[c] + 1e-5f) * bng[c] + bnb[c];
                v = fmaxf(v, 0.f);
            }
            d_x[(size_t)n * 256 + c] = __float2half_rn(v);
        }
    } else {
        int b = batch[n];
        #pragma unroll
        for (int j = 0; j < PL; j++) {
            int c = lane * PL + j;
            float v = acc[j] * invl + bias[c];
            atomicAdd(&d_gsum[b * 64 + c], v);
        }
        if (lane == 0) atomicAdd(&d_gcnt[b], 1.f);
    }
}

// ---------------- head ----------------
__global__ void head_kernel(const float* __restrict__ cw1, const float* __restrict__ cb1,
                            const float* __restrict__ cw2, const float* __restrict__ cb2,
                            float* __restrict__ out) {
    int g = blockIdx.x, j = threadIdx.x;
    __shared__ float sg[64], sh[64];
    float cntv = fmaxf(d_gcnt[g], 1.f);
    sg[j] = d_gsum[g * 64 + j] / cntv;
    __syncthreads();
    float a = cb1[j];
    #pragma unroll
    for (int k = 0; k < 64; k++) a = fmaf(sg[k], cw1[k * 64 + j], a);
    sh[j] = 0.5f * a * (1.f + erff(a * 0.70710678118654752440f));
    __syncthreads();
    if (j < 2) {
        float o = cb2[j];
        #pragma unroll
        for (int k = 0; k < 64; k++) o = fmaf(sh[k], cw2[k * 2 + j], o);
        out[g * 2 + j] = o;
    }
}

// ---------------- launch ----------------
extern "C" void kernel_launch(void* const* d_in, const int* in_sizes, int n_in,
                              void* d_out, int out_size) {
    (void)in_sizes; (void)n_in; (void)out_size;
    const float* x     = (const float*)d_in[0];
    const int*   ei    = (const int*)  d_in[1];
    const float* ea    = (const float*)d_in[2];
    const int*   batch = (const int*)  d_in[3];
    const float* W0  = (const float*)d_in[4];
    const float* as0 = (const float*)d_in[5];
    const float* ad0 = (const float*)d_in[6];
    const float* We0 = (const float*)d_in[7];
    const float* ae0 = (const float*)d_in[8];
    const float* b0  = (const float*)d_in[9];
    const float* W1  = (const float*)d_in[10];
    const float* as1 = (const float*)d_in[11];
    const float* ad1 = (const float*)d_in[12];
    const float* We1 = (const float*)d_in[13];
    const float* ae1 = (const float*)d_in[14];
    const float* b1  = (const float*)d_in[15];
    const float* W2  = (const float*)d_in[16];
    const float* as2 = (const float*)d_in[17];
    const float* ad2 = (const float*)d_in[18];
    const float* We2 = (const float*)d_in[19];
    const float* ae2 = (const float*)d_in[20];
    const float* b2  = (const float*)d_in[21];
    const float* bng = (const float*)d_in[22];
    const float* bnb = (const float*)d_in[23];
    const float* bnm = (const float*)d_in[24];
    const float* bnv = (const float*)d_in[25];
    const float* cw1 = (const float*)d_in[26];
    const float* cb1 = (const float*)d_in[27];
    const float* cw2 = (const float*)d_in[28];
    const float* cb2 = (const float*)d_in[29];
    float* out = (float*)d_out;

    const int SMEM_G01 = 2 * (128 * 80 + 128 * 80);   // 40960
    const int SMEM_G2  = 2 * (128 * 80 + 64 * 80);    // 30720
    cudaFuncSetAttribute(hmma_gemm<128, 256, KP0, 0, true>,  cudaFuncAttributeMaxDynamicSharedMemorySize, SMEM_G01);
    cudaFuncSetAttribute(hmma_gemm<128, 256, 256, 1, false>, cudaFuncAttributeMaxDynamicSharedMemorySize, SMEM_G01);
    cudaFuncSetAttribute(hmma_gemm<64, 64, 256, 2, false>,   cudaFuncAttributeMaxDynamicSharedMemorySize, SMEM_G2);

    // K1: prep (zero + xsplit + wsplit)
    prep_kernel<<<2048, 256>>>(x, W0, W1, W2);
    // K2: layer-0 GEMM + edge count (tail blocks)
    hmma_gemm<128, 256, KP0, 0, true><<<dim3(2, 300), 256, SMEM_G01>>>(ei, ea);
    // K3: scan + wd + attn0
    swa_kernel<<<2 + NN / 8, 1024>>>(as0, ad0, We0, ae0, We1, ae1, We2, ae2);
    // K4: fill + selfloop
    fillself_kernel<<<1700, 256>>>(ei, ea);
    // K5: agg0 (+BN+ReLU)
    agg_kernel<4><<<NN / 8, 256>>>(b0, bng, bnb, bnm, bnv, batch, 0, 1, 0);
    // K6-K8: layer 1
    hmma_gemm<128, 256, 256, 1, false><<<dim3(2, 200), 256, SMEM_G01>>>(ei, ea);
    attn_kernel<4><<<NN / 2, 256>>>(as1, ad1);
    agg_kernel<4><<<NN / 8, 256>>>(b1, bng, bnb, bnm, bnv, batch, 4, 1, 0);
    // K9-K11: layer 2 (+fused pool)
    hmma_gemm<64, 64, 256, 2, false><<<dim3(1, 200), 256, SMEM_G2>>>(ei, ea);
    attn_kernel<1><<<NN / 8, 256>>>(as2, ad2);
    agg_kernel<1><<<NN / 8, 256>>>(b2, bng, bnb, bnm, bnv, batch, 8, 0, 1);
    // K12: head
    head_kernel<<<GG, 64>>>(cw1, cb1, cw2, cb2, out);
}